// round 5
// baseline (speedup 1.0000x reference)
#include <cuda_runtime.h>
#include <cuda_bf16.h>
#include <math.h>
#include <stdint.h>

#define NN 100000
#define EE 500000
#define GG 2048
#define DIM 128
#define OUTD 64
#define BN_EPS 1e-5f

// ---------------- scratch (device globals; no allocation allowed) ----------------
__device__ float g_agg[NN * DIM];
__device__ float g_y[NN * DIM];
__device__ float g_h[NN * DIM];
__device__ float g_pool[GG * DIM];
__device__ float g_code[GG * OUTD];
__device__ float g_colsum[DIM];
__device__ float g_colsumsq[DIM];
__device__ float g_scale[DIM];
__device__ float g_shift[DIM];
__device__ int g_src[EE];
__device__ int g_dst[EE];
__device__ int g_batch[NN];
// formatted weights: [matrix][hi/lo][128 pairs * 32 lanes] of uint2
__device__ uint2 g_wfmt[4][2 * 4096];

// ---------------- helpers ----------------
__device__ __forceinline__ uint32_t pack_bf2(float a, float b) {
    __nv_bfloat162 t;
    t.x = __float2bfloat16(a);
    t.y = __float2bfloat16(b);
    return *reinterpret_cast<uint32_t*>(&t);
}
__device__ __forceinline__ void split_bf2(float a, float b, uint32_t& hi, uint32_t& lo) {
    __nv_bfloat16 ha = __float2bfloat16(a);
    __nv_bfloat16 hb = __float2bfloat16(b);
    float ra = a - __bfloat162float(ha);
    float rb = b - __bfloat162float(hb);
    __nv_bfloat162 th;
    th.x = ha; th.y = hb;
    hi = *reinterpret_cast<uint32_t*>(&th);
    lo = pack_bf2(ra, rb);
}
__device__ __forceinline__ void mma16816(float c[4], const uint32_t a[4], uint32_t b0, uint32_t b1) {
    asm volatile(
        "mma.sync.aligned.m16n8k16.row.col.f32.bf16.bf16.f32 "
        "{%0,%1,%2,%3}, {%4,%5,%6,%7}, {%8,%9}, {%0,%1,%2,%3};"
        : "+f"(c[0]), "+f"(c[1]), "+f"(c[2]), "+f"(c[3])
        : "r"(a[0]), "r"(a[1]), "r"(a[2]), "r"(a[3]), "r"(b0), "r"(b1));
}

// ---------------- weight formatter: all 4 W[128,128] -> mma B-frag hi/lo ----------------
// pair p = kstep*16 + ntile; lane holds B[k0..k0+1][n] (reg0) and B[k0+8..k0+9][n] (reg1)
// with k0 = kstep*16 + (lane&3)*2, n = ntile*8 + (lane>>2)
__global__ void format_w_all(const float* __restrict__ W0, const float* __restrict__ W1,
                             const float* __restrict__ W2, const float* __restrict__ W3,
                             uint2* __restrict__ wf_base) {
    int mat = blockIdx.x >> 2;
    const float* W = (mat == 0) ? W0 : (mat == 1) ? W1 : (mat == 2) ? W2 : W3;
    uint2* wf = wf_base + mat * 8192;
    int tid = threadIdx.x;
    int warp = tid >> 5, lane = tid & 31;
    int wglob = (blockIdx.x & 3) * 8 + warp;  // 0..31
#pragma unroll
    for (int i = 0; i < 4; i++) {
        int p = wglob * 4 + i;  // 0..127
        int kstep = p >> 4, ntile = p & 15;
        int k0 = kstep * 16 + (lane & 3) * 2;
        int n = ntile * 8 + (lane >> 2);
        float w00 = W[k0 * 128 + n];
        float w01 = W[(k0 + 1) * 128 + n];
        float w10 = W[(k0 + 8) * 128 + n];
        float w11 = W[(k0 + 9) * 128 + n];
        uint32_t h0, l0, h1, l1;
        split_bf2(w00, w01, h0, l0);
        split_bf2(w10, w11, h1, l1);
        wf[p * 32 + lane] = make_uint2(h0, h1);
        wf[4096 + p * 32 + lane] = make_uint2(l0, l1);
    }
}

// ---------------- index canonicalization (dtype-robust) ----------------
__device__ __forceinline__ bool is_int64_layout(const int* raw, int n_vals) {
    int nchk = n_vals < 64 ? n_vals : 64;
    for (int i = 0; i < nchk; i++)
        if (raw[2 * i + 1] != 0) return false;
    return true;
}

__global__ void convert_edges(const int* __restrict__ raw, int* __restrict__ src,
                              int* __restrict__ dst) {
    bool w = is_int64_layout(raw, 2 * EE);
    int i = blockIdx.x * blockDim.x + threadIdx.x;
    int stride = gridDim.x * blockDim.x;
    if (w) {
        const long long* r = (const long long*)raw;
        for (int e = i; e < EE; e += stride) {
            src[e] = (int)r[e];
            dst[e] = (int)r[EE + e];
        }
    } else {
        for (int e = i; e < EE; e += stride) {
            src[e] = raw[e];
            dst[e] = raw[EE + e];
        }
    }
}

// also zeroes pool + BN stat accumulators (keeps gemm at launch slot 5)
__global__ void convert_batch(const int* __restrict__ raw, int* __restrict__ out,
                              float* __restrict__ pool, float* __restrict__ colsum,
                              float* __restrict__ colsumsq) {
    bool w = is_int64_layout(raw, NN);
    int i = blockIdx.x * blockDim.x + threadIdx.x;
    int stride = gridDim.x * blockDim.x;
    if (w) {
        const long long* r = (const long long*)raw;
        for (int n = i; n < NN; n += stride) out[n] = (int)r[n];
    } else {
        for (int n = i; n < NN; n += stride) out[n] = raw[n];
    }
    if (i < GG * DIM / 4) ((float4*)pool)[i] = make_float4(0.f, 0.f, 0.f, 0.f);
    if (i < DIM) { colsum[i] = 0.f; colsumsq[i] = 0.f; }
}

// ---------------- utility kernels ----------------
__global__ void zero_f(float* __restrict__ p, int n) {
    int i = blockIdx.x * blockDim.x + threadIdx.x;
    int stride = gridDim.x * blockDim.x;
    float4* p4 = (float4*)p;
    int n4 = n >> 2;
    for (int k = i; k < n4; k += stride) p4[k] = make_float4(0.f, 0.f, 0.f, 0.f);
}

__global__ void zero_stats(float* __restrict__ a, float* __restrict__ b) {
    int i = threadIdx.x;
    if (i < DIM) { a[i] = 0.f; b[i] = 0.f; }
}

// ---------------- edge aggregation ----------------
__global__ void edge_agg(const float* __restrict__ h, const int* __restrict__ src,
                         const int* __restrict__ dst, float* __restrict__ agg, int E) {
    int t = blockIdx.x * blockDim.x + threadIdx.x;
    int e = t >> 5;
    int lane = t & 31;
    if (e >= E) return;
    int s = src[e];
    int d = dst[e];
    if ((unsigned)s >= NN || (unsigned)d >= NN) return;
    float4 v = ((const float4*)(h + (size_t)s * DIM))[lane];
    float* a = agg + (size_t)d * DIM + lane * 4;
    atomicAdd(a + 0, v.x);
    atomicAdd(a + 1, v.y);
    atomicAdd(a + 2, v.z);
    atomicAdd(a + 3, v.w);
}

// ---------------- pooling ----------------
__global__ void pool_kernel(const float* __restrict__ h, const int* __restrict__ batch,
                            float* __restrict__ pool, int n_nodes) {
    int t = blockIdx.x * blockDim.x + threadIdx.x;
    int n = t >> 5;
    int lane = t & 31;
    if (n >= n_nodes) return;
    int g = batch[n];
    if ((unsigned)g >= GG) return;
    float4 v = ((const float4*)(h + (size_t)n * DIM))[lane];
    float* p = pool + (size_t)g * DIM + lane * 4;
    atomicAdd(p + 0, v.x);
    atomicAdd(p + 1, v.y);
    atomicAdd(p + 2, v.z);
    atomicAdd(p + 3, v.w);
}

// ---------------- BN finalize ----------------
__global__ void bn_finalize(const float* __restrict__ colsum, const float* __restrict__ colsumsq,
                            const float* __restrict__ gamma, const float* __restrict__ beta,
                            float* __restrict__ scale, float* __restrict__ shift, int M) {
    int c = threadIdx.x;
    if (c >= DIM) return;
    float invM = 1.f / (float)M;
    float mean = colsum[c] * invM;
    float var = colsumsq[c] * invM - mean * mean;
    float sc = gamma[c] * rsqrtf(var + BN_EPS);
    scale[c] = sc;
    shift[c] = beta[c] - mean * sc;
}

// ---------------- mma GEMM: C[M,128] = act(A'[M,128] @ W[128,128] + b) ----------------
// bf16 hi/lo 3-pass. IN_MODE 1: A' = A0 + A1 ; 2: A' = relu(scale*A0 + shift)
// 512 threads / 16 warps; CTA tile 256 rows; warp w computes rows [w*16, w*16+16) x 128 cols.
// STATS: accumulate column sum/sumsq of pre-activation y.
#define ROWS_CTA 256
#define AS_STRIDE 136
#define OFF_AS 0
#define OFF_WF (ROWS_CTA * AS_STRIDE * 4)         // 139264
#define OFF_BIAS (OFF_WF + 65536)                 // 204800
#define MMA_SMEM (OFF_BIAS + 512)                 // 205312

template <int IN_MODE, bool OUT_RELU, bool STATS>
__global__ __launch_bounds__(512, 1) void gemm_mma(
    const float* __restrict__ A0, const float* __restrict__ A1,
    const float* __restrict__ scale, const float* __restrict__ shift,
    const uint2* __restrict__ wfmt, const float* __restrict__ bias,
    float* __restrict__ C, int M,
    float* __restrict__ colsum, float* __restrict__ colsumsq) {
    extern __shared__ char smc[];
    float* As = (float*)(smc + OFF_AS);
    uint2* Wf = (uint2*)(smc + OFF_WF);
    float* sb = (float*)(smc + OFF_BIAS);
    int tid = threadIdx.x;
    int row0 = blockIdx.x * ROWS_CTA;

    // stage formatted W (8192 uint2 = 4096 uint4)
    {
        const uint4* srcv = (const uint4*)wfmt;
        uint4* dstv = (uint4*)Wf;
#pragma unroll
        for (int i = 0; i < 8; i++) dstv[tid + i * 512] = srcv[tid + i * 512];
    }
    if (tid < 32) ((float4*)sb)[tid] = ((const float4*)bias)[tid];
    // stage A tile (with input transform), fp32, padded stride 136
    {
#pragma unroll
        for (int i = 0; i < 16; i++) {
            int idx4 = tid + i * 512;  // 8192 float4
            int row = idx4 >> 5, c4 = idx4 & 31;
            int gr = row0 + row;
            float4 v = make_float4(0.f, 0.f, 0.f, 0.f);
            if (gr < M) {
                v = ((const float4*)A0)[(size_t)gr * 32 + c4];
                if (IN_MODE == 1) {
                    float4 u = ((const float4*)A1)[(size_t)gr * 32 + c4];
                    v.x += u.x; v.y += u.y; v.z += u.z; v.w += u.w;
                } else if (IN_MODE == 2) {
                    const float4 sc = ((const float4*)scale)[c4];
                    const float4 sh = ((const float4*)shift)[c4];
                    v.x = fmaxf(v.x * sc.x + sh.x, 0.f);
                    v.y = fmaxf(v.y * sc.y + sh.y, 0.f);
                    v.z = fmaxf(v.z * sc.z + sh.z, 0.f);
                    v.w = fmaxf(v.w * sc.w + sh.w, 0.f);
                }
            }
            *(float4*)(As + row * AS_STRIDE + c4 * 4) = v;
        }
    }
    __syncthreads();

    int warp = tid >> 5, lane = tid & 31;
    int r_lo = warp * 16 + (lane >> 2);
    const uint2* WfHi = Wf;
    const uint2* WfLo = Wf + 4096;

    float c[16][4];
#pragma unroll
    for (int i = 0; i < 16; i++)
#pragma unroll
        for (int j = 0; j < 4; j++) c[i][j] = 0.f;

#pragma unroll
    for (int kstep = 0; kstep < 8; kstep++) {
        int cb = (lane & 3) * 2 + kstep * 16;
        float2 f0 = *(const float2*)(As + r_lo * AS_STRIDE + cb);
        float2 f1 = *(const float2*)(As + (r_lo + 8) * AS_STRIDE + cb);
        float2 f2 = *(const float2*)(As + r_lo * AS_STRIDE + cb + 8);
        float2 f3 = *(const float2*)(As + (r_lo + 8) * AS_STRIDE + cb + 8);
        uint32_t ah[4], al[4];
        split_bf2(f0.x, f0.y, ah[0], al[0]);
        split_bf2(f1.x, f1.y, ah[1], al[1]);
        split_bf2(f2.x, f2.y, ah[2], al[2]);
        split_bf2(f3.x, f3.y, ah[3], al[3]);
#pragma unroll
        for (int ntile = 0; ntile < 16; ntile++) {
            uint2 bh = WfHi[(kstep * 16 + ntile) * 32 + lane];
            uint2 bl = WfLo[(kstep * 16 + ntile) * 32 + lane];
            mma16816(c[ntile], ah, bh.x, bh.y);
            mma16816(c[ntile], al, bh.x, bh.y);
            mma16816(c[ntile], ah, bl.x, bl.y);
        }
    }

    // epilogue
    int gr0 = row0 + warp * 16 + (lane >> 2);
    int gr1 = gr0 + 8;
    bool v0 = gr0 < M, v1 = gr1 < M;
#pragma unroll
    for (int ntile = 0; ntile < 16; ntile++) {
        int col0 = ntile * 8 + (lane & 3) * 2;
        float y0 = c[ntile][0] + sb[col0];
        float y1 = c[ntile][1] + sb[col0 + 1];
        float y2 = c[ntile][2] + sb[col0];
        float y3 = c[ntile][3] + sb[col0 + 1];
        float o0 = y0, o1 = y1, o2 = y2, o3 = y3;
        if (OUT_RELU) {
            o0 = fmaxf(o0, 0.f); o1 = fmaxf(o1, 0.f);
            o2 = fmaxf(o2, 0.f); o3 = fmaxf(o3, 0.f);
        }
        if (v0) *(float2*)(C + (size_t)gr0 * 128 + col0) = make_float2(o0, o1);
        if (v1) *(float2*)(C + (size_t)gr1 * 128 + col0) = make_float2(o2, o3);
        if (STATS) {
            float s0 = (v0 ? y0 : 0.f) + (v1 ? y2 : 0.f);
            float s1 = (v0 ? y1 : 0.f) + (v1 ? y3 : 0.f);
            float q0 = (v0 ? y0 * y0 : 0.f) + (v1 ? y2 * y2 : 0.f);
            float q1 = (v0 ? y1 * y1 : 0.f) + (v1 ? y3 * y3 : 0.f);
#pragma unroll
            for (int off = 4; off < 32; off <<= 1) {
                s0 += __shfl_xor_sync(0xffffffffu, s0, off);
                s1 += __shfl_xor_sync(0xffffffffu, s1, off);
                q0 += __shfl_xor_sync(0xffffffffu, q0, off);
                q1 += __shfl_xor_sync(0xffffffffu, q1, off);
            }
            if (lane < 4) {
                atomicAdd(&colsum[col0], s0);
                atomicAdd(&colsum[col0 + 1], s1);
                atomicAdd(&colsumsq[col0], q0);
                atomicAdd(&colsumsq[col0 + 1], q1);
            }
        }
    }
}

// ---------------- code MLP branch ----------------
__global__ void code_mlp(const float* __restrict__ code_x,
                         const float* __restrict__ w1, const float* __restrict__ b1,
                         const float* __restrict__ w2, const float* __restrict__ b2,
                         const float* __restrict__ w3, const float* __restrict__ b3,
                         float* __restrict__ code_out) {
    __shared__ float buf0[128], buf1[128];
    __shared__ float red[64];
    __shared__ float s_mx, s_lse;
    int g = blockIdx.x, j = threadIdx.x;
    buf0[j] = code_x[(size_t)g * 128 + j];
    __syncthreads();
    float acc = b1[j];
    for (int k = 0; k < 128; k++) acc += buf0[k] * w1[k * 128 + j];
    buf1[j] = fmaxf(acc, 0.f);
    __syncthreads();
    float acc2 = b2[j];
    for (int k = 0; k < 128; k++) acc2 += buf1[k] * w2[k * 128 + j];
    buf0[j] = fmaxf(acc2, 0.f);
    __syncthreads();
    float v = 0.f;
    if (j < 64) {
        v = b3[j];
        for (int k = 0; k < 128; k++) v += buf0[k] * w3[k * 64 + j];
        red[j] = v;
    }
    __syncthreads();
    if (j == 0) {
        float m = red[0];
        for (int i = 1; i < 64; i++) m = fmaxf(m, red[i]);
        float s = 0.f;
        for (int i = 0; i < 64; i++) s += expf(red[i] - m);
        s_mx = m;
        s_lse = logf(s);
    }
    __syncthreads();
    if (j < 64) code_out[(size_t)g * 64 + j] = v - s_mx - s_lse;
}

// ---------------- head ----------------
__global__ void head_kernel(const float* __restrict__ pool,
                            const float* __restrict__ l1w, const float* __restrict__ l1b,
                            const float* __restrict__ l2w, const float* __restrict__ l2b,
                            const float* __restrict__ code,
                            const float* __restrict__ finw, const float* __restrict__ finb,
                            float* __restrict__ out) {
    __shared__ float p[128], t[128], cc[128];
    __shared__ float r0[128], r1[128];
    int g = blockIdx.x, j = threadIdx.x;
    p[j] = pool[(size_t)g * 128 + j];
    __syncthreads();
    float a = l1b[j];
    for (int k = 0; k < 128; k++) a += p[k] * l1w[k * 128 + j];
    t[j] = fmaxf(a, 0.f);
    __syncthreads();
    if (j < 64) {
        float v = l2b[j];
        for (int k = 0; k < 128; k++) v += t[k] * l2w[k * 64 + j];
        cc[64 + j] = v;
        cc[j] = code[(size_t)g * 64 + j];
    }
    __syncthreads();
    r0[j] = cc[j] * finw[j * 2 + 0];
    r1[j] = cc[j] * finw[j * 2 + 1];
    __syncthreads();
    if (j == 0) {
        float o0 = finb[0], o1 = finb[1];
        for (int k = 0; k < 128; k++) { o0 += r0[k]; o1 += r1[k]; }
        float m = fmaxf(o0, o1);
        float l = m + logf(expf(o0 - m) + expf(o1 - m));
        out[(size_t)g * 2 + 0] = o0 - l;
        out[(size_t)g * 2 + 1] = o1 - l;
    }
}

// ---------------- launcher ----------------
extern "C" void kernel_launch(void* const* d_in, const int* in_sizes, int n_in,
                              void* d_out, int out_size) {
    const float* x = (const float*)d_in[0];
    const int* ei_raw = (const int*)d_in[1];
    const int* batch_raw = (const int*)d_in[2];
    const float* code_x = (const float*)d_in[3];
    const float* c1_w1 = (const float*)d_in[4];
    const float* c1_b1 = (const float*)d_in[5];
    const float* c1_g = (const float*)d_in[6];
    const float* c1_be = (const float*)d_in[7];
    const float* c1_w2 = (const float*)d_in[8];
    const float* c1_b2 = (const float*)d_in[9];
    const float* c2_w1 = (const float*)d_in[10];
    const float* c2_b1 = (const float*)d_in[11];
    const float* c2_g = (const float*)d_in[12];
    const float* c2_be = (const float*)d_in[13];
    const float* c2_w2 = (const float*)d_in[14];
    const float* c2_b2 = (const float*)d_in[15];
    const float* gl1_w = (const float*)d_in[16];
    const float* gl1_b = (const float*)d_in[17];
    const float* gl2_w = (const float*)d_in[18];
    const float* gl2_b = (const float*)d_in[19];
    const float* fc1_w = (const float*)d_in[20];
    const float* fc1_b = (const float*)d_in[21];
    const float* fc2_w = (const float*)d_in[22];
    const float* fc2_b = (const float*)d_in[23];
    const float* fc3_w = (const float*)d_in[24];
    const float* fc3_b = (const float*)d_in[25];
    const float* fin_w = (const float*)d_in[26];
    const float* fin_b = (const float*)d_in[27];
    float* out = (float*)d_out;

    float *agg, *y, *h, *pool, *code, *colsum, *colsumsq, *scale, *shift;
    int *srcp, *dstp, *batchp;
    uint2* wfmt;
    cudaGetSymbolAddress((void**)&agg, g_agg);
    cudaGetSymbolAddress((void**)&y, g_y);
    cudaGetSymbolAddress((void**)&h, g_h);
    cudaGetSymbolAddress((void**)&pool, g_pool);
    cudaGetSymbolAddress((void**)&code, g_code);
    cudaGetSymbolAddress((void**)&colsum, g_colsum);
    cudaGetSymbolAddress((void**)&colsumsq, g_colsumsq);
    cudaGetSymbolAddress((void**)&scale, g_scale);
    cudaGetSymbolAddress((void**)&shift, g_shift);
    cudaGetSymbolAddress((void**)&srcp, g_src);
    cudaGetSymbolAddress((void**)&dstp, g_dst);
    cudaGetSymbolAddress((void**)&batchp, g_batch);
    cudaGetSymbolAddress((void**)&wfmt, g_wfmt);

    cudaFuncSetAttribute(gemm_mma<1, false, true>, cudaFuncAttributeMaxDynamicSharedMemorySize, MMA_SMEM);
    cudaFuncSetAttribute(gemm_mma<2, true, false>, cudaFuncAttributeMaxDynamicSharedMemorySize, MMA_SMEM);

    const int tc_blocks = (NN + ROWS_CTA - 1) / ROWS_CTA;  // 391
    const int edge_blocks = (EE * 32 + 255) / 256;         // 62500
    const int pool_blocks = (NN * 32 + 255) / 256;         // 12500

    // launch slots 0-4 (keeps gemm_mma at slot 5 for the profiler's -s 5 window)
    convert_edges<<<512, 256>>>(ei_raw, srcp, dstp);                                   // 0
    convert_batch<<<256, 256>>>(batch_raw, batchp, pool, colsum, colsumsq);            // 1
    format_w_all<<<16, 256>>>(c1_w1, c1_w2, c2_w1, c2_w2, wfmt);                       // 2
    zero_f<<<4096, 256>>>(agg, NN * DIM);                                              // 3
    edge_agg<<<edge_blocks, 256>>>(x, srcp, dstp, agg, EE);                            // 4

    // ---- conv1 ----
    gemm_mma<1, false, true><<<tc_blocks, 512, MMA_SMEM>>>(                            // 5 (profiled)
        x, agg, nullptr, nullptr, wfmt + 0 * 8192, c1_b1, y, NN, colsum, colsumsq);
    code_mlp<<<GG, 128>>>(code_x, fc1_w, fc1_b, fc2_w, fc2_b, fc3_w, fc3_b, code);
    bn_finalize<<<1, 128>>>(colsum, colsumsq, c1_g, c1_be, scale, shift, NN);
    gemm_mma<2, true, false><<<tc_blocks, 512, MMA_SMEM>>>(
        y, nullptr, scale, shift, wfmt + 1 * 8192, c1_b2, h, NN, nullptr, nullptr);

    // ---- conv2 ----
    zero_f<<<4096, 256>>>(agg, NN * DIM);
    edge_agg<<<edge_blocks, 256>>>(h, srcp, dstp, agg, EE);
    zero_stats<<<1, 128>>>(colsum, colsumsq);
    gemm_mma<1, false, true><<<tc_blocks, 512, MMA_SMEM>>>(
        h, agg, nullptr, nullptr, wfmt + 2 * 8192, c2_b1, y, NN, colsum, colsumsq);
    bn_finalize<<<1, 128>>>(colsum, colsumsq, c2_g, c2_be, scale, shift, NN);
    gemm_mma<2, true, false><<<tc_blocks, 512, MMA_SMEM>>>(
        y, nullptr, scale, shift, wfmt + 3 * 8192, c2_b2, h, NN, nullptr, nullptr);

    // ---- pool + heads ----
    pool_kernel<<<pool_blocks, 256>>>(h, batchp, pool, NN);
    head_kernel<<<GG, 128>>>(pool, gl1_w, gl1_b, gl2_w, gl2_b, code, fin_w, fin_b, out);
}

// round 6
// speedup vs baseline: 1.1093x; 1.1093x over previous
#include <cuda_runtime.h>
#include <math.h>
#include <stdint.h>

#define NN 100000
#define EE 500000
#define GG 2048
#define DIM 128
#define OUTD 64
#define BN_EPS 1e-5f

// ---------------- scratch (device globals; no allocation allowed) ----------------
__device__ float g_agg[NN * DIM];
__device__ float g_y[NN * DIM];
__device__ float g_h[NN * DIM];
__device__ float g_pool[GG * DIM];
__device__ float g_code[GG * OUTD];
__device__ float g_colsum1[DIM];
__device__ float g_colsumsq1[DIM];
__device__ float g_colsum2[DIM];
__device__ float g_colsumsq2[DIM];
__device__ float g_scale[DIM];
__device__ float g_shift[DIM];
__device__ int g_src[EE];
__device__ int g_dst[EE];
__device__ int g_batch[NN];

// ---------------- vector reduction helper (sm_90+) ----------------
__device__ __forceinline__ void red_add_v4(float* p, float a, float b, float c, float d) {
    asm volatile("red.global.add.v4.f32 [%0], {%1, %2, %3, %4};"
                 :: "l"(p), "f"(a), "f"(b), "f"(c), "f"(d) : "memory");
}

// ---------------- index canonicalization (dtype-robust) ----------------
__device__ __forceinline__ bool is_int64_layout(const int* raw, int n_vals) {
    int nchk = n_vals < 64 ? n_vals : 64;
    for (int i = 0; i < nchk; i++)
        if (raw[2 * i + 1] != 0) return false;
    return true;
}

__global__ void convert_edges(const int* __restrict__ raw, int* __restrict__ src,
                              int* __restrict__ dst) {
    bool w = is_int64_layout(raw, 2 * EE);
    int i = blockIdx.x * blockDim.x + threadIdx.x;
    int stride = gridDim.x * blockDim.x;
    if (w) {
        const long long* r = (const long long*)raw;
        for (int e = i; e < EE; e += stride) {
            src[e] = (int)r[e];
            dst[e] = (int)r[EE + e];
        }
    } else {
        for (int e = i; e < EE; e += stride) {
            src[e] = raw[e];
            dst[e] = raw[EE + e];
        }
    }
}

// also zeroes pool + both BN stat accumulator sets
__global__ void convert_batch(const int* __restrict__ raw, int* __restrict__ out,
                              float* __restrict__ pool,
                              float* __restrict__ cs1, float* __restrict__ cq1,
                              float* __restrict__ cs2, float* __restrict__ cq2) {
    bool w = is_int64_layout(raw, NN);
    int i = blockIdx.x * blockDim.x + threadIdx.x;
    int stride = gridDim.x * blockDim.x;
    if (w) {
        const long long* r = (const long long*)raw;
        for (int n = i; n < NN; n += stride) out[n] = (int)r[n];
    } else {
        for (int n = i; n < NN; n += stride) out[n] = raw[n];
    }
    if (i < GG * DIM / 4) ((float4*)pool)[i] = make_float4(0.f, 0.f, 0.f, 0.f);
    if (i < DIM) { cs1[i] = 0.f; cq1[i] = 0.f; cs2[i] = 0.f; cq2[i] = 0.f; }
}

// ---------------- utility ----------------
__global__ void zero_f(float* __restrict__ p, int n) {
    int i = blockIdx.x * blockDim.x + threadIdx.x;
    int stride = gridDim.x * blockDim.x;
    float4* p4 = (float4*)p;
    int n4 = n >> 2;
    for (int k = i; k < n4; k += stride) p4[k] = make_float4(0.f, 0.f, 0.f, 0.f);
}

// ---------------- edge aggregation: agg[dst] += h[src]  (32 lanes/edge, red.v4) --------
__global__ void edge_agg(const float* __restrict__ h, const int* __restrict__ src,
                         const int* __restrict__ dst, float* __restrict__ agg, int E) {
    int t = blockIdx.x * blockDim.x + threadIdx.x;
    int e = t >> 5;
    int lane = t & 31;
    if (e >= E) return;
    int s = src[e];
    int d = dst[e];
    if ((unsigned)s >= NN || (unsigned)d >= NN) return;
    float4 v = ((const float4*)(h + (size_t)s * DIM))[lane];
    red_add_v4(agg + (size_t)d * DIM + lane * 4, v.x, v.y, v.z, v.w);
}

// ---------------- BN finalize ----------------
__global__ void bn_finalize(const float* __restrict__ colsum, const float* __restrict__ colsumsq,
                            const float* __restrict__ gamma, const float* __restrict__ beta,
                            float* __restrict__ scale, float* __restrict__ shift, int M) {
    int c = threadIdx.x;
    if (c >= DIM) return;
    float invM = 1.f / (float)M;
    float mean = colsum[c] * invM;
    float var = colsumsq[c] * invM - mean * mean;
    float sc = gamma[c] * rsqrtf(var + BN_EPS);
    scale[c] = sc;
    shift[c] = beta[c] - mean * sc;
}

// ---------------- FFMA GEMM: C[M,128] = act(A'[M,128] @ W[128,128] + b) ----------------
// IN_MODE 1: A' = A0 + A1 ; 2: A' = relu(scale*A0 + shift)
// 256 threads, 64-row tile, each thread computes 8 rows x 4 cols.
// STATS: accumulate column sum/sumsq of pre-activation output.
// POOL: skip C write; red.v4 rows into pool[batch[row]].
#define GEMM_SMEM ((128 * 128 + 64 * 128) * 4)
template <int IN_MODE, bool OUT_RELU, bool STATS, bool POOL>
__global__ __launch_bounds__(256, 2) void gemm128(
    const float* __restrict__ A0, const float* __restrict__ A1,
    const float* __restrict__ scale, const float* __restrict__ shift,
    const float* __restrict__ W, const float* __restrict__ bias,
    float* __restrict__ C, int M,
    float* __restrict__ colsum, float* __restrict__ colsumsq,
    const int* __restrict__ batch, float* __restrict__ pool) {
    extern __shared__ float sm[];
    float* Wsm = sm;             // 128*128
    float* Asm = sm + 128 * 128; // 64*128
    __shared__ float scs[128], scq[128];
    int tid = threadIdx.x;
    int row0 = blockIdx.x * 64;

    // stage W (16384 floats, float4)
    {
        const float4* Wv = (const float4*)W;
        float4* Wsv = (float4*)Wsm;
#pragma unroll
        for (int i = 0; i < 16; i++) Wsv[tid + i * 256] = Wv[tid + i * 256];
    }
    if (STATS && tid < 128) { scs[tid] = 0.f; scq[tid] = 0.f; }
    // stage A tile with input transform (2048 float4)
    {
        float4* Asv = (float4*)Asm;
#pragma unroll
        for (int i = 0; i < 8; i++) {
            int idx = tid + i * 256;
            int r = idx >> 5;
            int c4 = idx & 31;
            int gr = row0 + r;
            float4 v = make_float4(0.f, 0.f, 0.f, 0.f);
            if (gr < M) {
                v = ((const float4*)A0)[(size_t)gr * 32 + c4];
                if (IN_MODE == 1) {
                    float4 u = ((const float4*)A1)[(size_t)gr * 32 + c4];
                    v.x += u.x; v.y += u.y; v.z += u.z; v.w += u.w;
                } else if (IN_MODE == 2) {
                    float4 sc = ((const float4*)scale)[c4];
                    float4 sh = ((const float4*)shift)[c4];
                    v.x = fmaxf(v.x * sc.x + sh.x, 0.f);
                    v.y = fmaxf(v.y * sc.y + sh.y, 0.f);
                    v.z = fmaxf(v.z * sc.z + sh.z, 0.f);
                    v.w = fmaxf(v.w * sc.w + sh.w, 0.f);
                }
            }
            Asv[idx] = v;
        }
    }
    __syncthreads();

    int cid = tid & 31;  // column group: cols cid*4..+3
    int rid = tid >> 5;  // row group: rows rid*8..+7
    float acc[8][4];
#pragma unroll
    for (int i = 0; i < 8; i++)
#pragma unroll
        for (int j = 0; j < 4; j++) acc[i][j] = 0.f;

    const float4* Asv = (const float4*)Asm;
    const float4* Wsv = (const float4*)Wsm;
#pragma unroll
    for (int k4 = 0; k4 < 32; k4++) {
        float4 av[8];
#pragma unroll
        for (int i = 0; i < 8; i++) av[i] = Asv[(rid * 8 + i) * 32 + k4];
#pragma unroll
        for (int kk = 0; kk < 4; kk++) {
            float4 wv = Wsv[(k4 * 4 + kk) * 32 + cid];
#pragma unroll
            for (int i = 0; i < 8; i++) {
                float a = (kk == 0) ? av[i].x : (kk == 1) ? av[i].y : (kk == 2) ? av[i].z : av[i].w;
                acc[i][0] += a * wv.x;
                acc[i][1] += a * wv.y;
                acc[i][2] += a * wv.z;
                acc[i][3] += a * wv.w;
            }
        }
    }

    float4 bv = ((const float4*)bias)[cid];
    float cs[4] = {0.f, 0.f, 0.f, 0.f};
    float cq[4] = {0.f, 0.f, 0.f, 0.f};
#pragma unroll
    for (int i = 0; i < 8; i++) {
        int gr = row0 + rid * 8 + i;
        if (gr < M) {
            float y0 = acc[i][0] + bv.x;
            float y1 = acc[i][1] + bv.y;
            float y2 = acc[i][2] + bv.z;
            float y3 = acc[i][3] + bv.w;
            if (STATS) {
                cs[0] += y0; cs[1] += y1; cs[2] += y2; cs[3] += y3;
                cq[0] += y0 * y0; cq[1] += y1 * y1; cq[2] += y2 * y2; cq[3] += y3 * y3;
            }
            float4 o;
            o.x = OUT_RELU ? fmaxf(y0, 0.f) : y0;
            o.y = OUT_RELU ? fmaxf(y1, 0.f) : y1;
            o.z = OUT_RELU ? fmaxf(y2, 0.f) : y2;
            o.w = OUT_RELU ? fmaxf(y3, 0.f) : y3;
            if (POOL) {
                int g = batch[gr];
                if ((unsigned)g < GG)
                    red_add_v4(pool + (size_t)g * DIM + cid * 4, o.x, o.y, o.z, o.w);
            } else {
                ((float4*)C)[(size_t)gr * 32 + cid] = o;
            }
        }
    }
    if (STATS) {
#pragma unroll
        for (int j = 0; j < 4; j++) {
            atomicAdd(&scs[cid * 4 + j], cs[j]);
            atomicAdd(&scq[cid * 4 + j], cq[j]);
        }
        __syncthreads();
        if (tid < 128) {
            atomicAdd(&colsum[tid], scs[tid]);
            atomicAdd(&colsumsq[tid], scq[tid]);
        }
    }
}

// ---------------- code MLP branch ----------------
__global__ void code_mlp(const float* __restrict__ code_x,
                         const float* __restrict__ w1, const float* __restrict__ b1,
                         const float* __restrict__ w2, const float* __restrict__ b2,
                         const float* __restrict__ w3, const float* __restrict__ b3,
                         float* __restrict__ code_out) {
    __shared__ float buf0[128], buf1[128];
    __shared__ float red[64];
    __shared__ float s_mx, s_lse;
    int g = blockIdx.x, j = threadIdx.x;
    buf0[j] = code_x[(size_t)g * 128 + j];
    __syncthreads();
    float acc = b1[j];
    for (int k = 0; k < 128; k++) acc += buf0[k] * w1[k * 128 + j];
    buf1[j] = fmaxf(acc, 0.f);
    __syncthreads();
    float acc2 = b2[j];
    for (int k = 0; k < 128; k++) acc2 += buf1[k] * w2[k * 128 + j];
    buf0[j] = fmaxf(acc2, 0.f);
    __syncthreads();
    float v = 0.f;
    if (j < 64) {
        v = b3[j];
        for (int k = 0; k < 128; k++) v += buf0[k] * w3[k * 64 + j];
        red[j] = v;
    }
    __syncthreads();
    if (j == 0) {
        float m = red[0];
        for (int i = 1; i < 64; i++) m = fmaxf(m, red[i]);
        float s = 0.f;
        for (int i = 0; i < 64; i++) s += expf(red[i] - m);
        s_mx = m;
        s_lse = logf(s);
    }
    __syncthreads();
    if (j < 64) code_out[(size_t)g * 64 + j] = v - s_mx - s_lse;
}

// ---------------- head ----------------
__global__ void head_kernel(const float* __restrict__ pool,
                            const float* __restrict__ l1w, const float* __restrict__ l1b,
                            const float* __restrict__ l2w, const float* __restrict__ l2b,
                            const float* __restrict__ code,
                            const float* __restrict__ finw, const float* __restrict__ finb,
                            float* __restrict__ out) {
    __shared__ float p[128], t[128], cc[128];
    __shared__ float r0[128], r1[128];
    int g = blockIdx.x, j = threadIdx.x;
    p[j] = pool[(size_t)g * 128 + j];
    __syncthreads();
    float a = l1b[j];
    for (int k = 0; k < 128; k++) a += p[k] * l1w[k * 128 + j];
    t[j] = fmaxf(a, 0.f);
    __syncthreads();
    if (j < 64) {
        float v = l2b[j];
        for (int k = 0; k < 128; k++) v += t[k] * l2w[k * 64 + j];
        cc[64 + j] = v;
        cc[j] = code[(size_t)g * 64 + j];
    }
    __syncthreads();
    r0[j] = cc[j] * finw[j * 2 + 0];
    r1[j] = cc[j] * finw[j * 2 + 1];
    __syncthreads();
    if (j == 0) {
        float o0 = finb[0], o1 = finb[1];
        for (int k = 0; k < 128; k++) { o0 += r0[k]; o1 += r1[k]; }
        float m = fmaxf(o0, o1);
        float l = m + logf(expf(o0 - m) + expf(o1 - m));
        out[(size_t)g * 2 + 0] = o0 - l;
        out[(size_t)g * 2 + 1] = o1 - l;
    }
}

// ---------------- launcher ----------------
extern "C" void kernel_launch(void* const* d_in, const int* in_sizes, int n_in,
                              void* d_out, int out_size) {
    const float* x = (const float*)d_in[0];
    const int* ei_raw = (const int*)d_in[1];
    const int* batch_raw = (const int*)d_in[2];
    const float* code_x = (const float*)d_in[3];
    const float* c1_w1 = (const float*)d_in[4];
    const float* c1_b1 = (const float*)d_in[5];
    const float* c1_g = (const float*)d_in[6];
    const float* c1_be = (const float*)d_in[7];
    const float* c1_w2 = (const float*)d_in[8];
    const float* c1_b2 = (const float*)d_in[9];
    const float* c2_w1 = (const float*)d_in[10];
    const float* c2_b1 = (const float*)d_in[11];
    const float* c2_g = (const float*)d_in[12];
    const float* c2_be = (const float*)d_in[13];
    const float* c2_w2 = (const float*)d_in[14];
    const float* c2_b2 = (const float*)d_in[15];
    const float* gl1_w = (const float*)d_in[16];
    const float* gl1_b = (const float*)d_in[17];
    const float* gl2_w = (const float*)d_in[18];
    const float* gl2_b = (const float*)d_in[19];
    const float* fc1_w = (const float*)d_in[20];
    const float* fc1_b = (const float*)d_in[21];
    const float* fc2_w = (const float*)d_in[22];
    const float* fc2_b = (const float*)d_in[23];
    const float* fc3_w = (const float*)d_in[24];
    const float* fc3_b = (const float*)d_in[25];
    const float* fin_w = (const float*)d_in[26];
    const float* fin_b = (const float*)d_in[27];
    float* out = (float*)d_out;

    float *agg, *y, *h, *pool, *code, *cs1, *cq1, *cs2, *cq2, *scale, *shift;
    int *srcp, *dstp, *batchp;
    cudaGetSymbolAddress((void**)&agg, g_agg);
    cudaGetSymbolAddress((void**)&y, g_y);
    cudaGetSymbolAddress((void**)&h, g_h);
    cudaGetSymbolAddress((void**)&pool, g_pool);
    cudaGetSymbolAddress((void**)&code, g_code);
    cudaGetSymbolAddress((void**)&cs1, g_colsum1);
    cudaGetSymbolAddress((void**)&cq1, g_colsumsq1);
    cudaGetSymbolAddress((void**)&cs2, g_colsum2);
    cudaGetSymbolAddress((void**)&cq2, g_colsumsq2);
    cudaGetSymbolAddress((void**)&scale, g_scale);
    cudaGetSymbolAddress((void**)&shift, g_shift);
    cudaGetSymbolAddress((void**)&srcp, g_src);
    cudaGetSymbolAddress((void**)&dstp, g_dst);
    cudaGetSymbolAddress((void**)&batchp, g_batch);

    cudaFuncSetAttribute(gemm128<1, false, true, false>, cudaFuncAttributeMaxDynamicSharedMemorySize, GEMM_SMEM);
    cudaFuncSetAttribute(gemm128<2, true, false, false>, cudaFuncAttributeMaxDynamicSharedMemorySize, GEMM_SMEM);
    cudaFuncSetAttribute(gemm128<2, true, false, true>, cudaFuncAttributeMaxDynamicSharedMemorySize, GEMM_SMEM);

    const int gemm_blocks = (NN + 63) / 64;           // 1563
    const int edge_blocks = (EE * 32 + 255) / 256;    // 62500

    convert_edges<<<512, 256>>>(ei_raw, srcp, dstp);                                   // 0
    convert_batch<<<256, 256>>>(batch_raw, batchp, pool, cs1, cq1, cs2, cq2);          // 1
    zero_f<<<4096, 256>>>(agg, NN * DIM);                                              // 2
    edge_agg<<<edge_blocks, 256>>>(x, srcp, dstp, agg, EE);                            // 3 (profiled)
    code_mlp<<<GG, 128>>>(code_x, fc1_w, fc1_b, fc2_w, fc2_b, fc3_w, fc3_b, code);     // 4

    // ---- conv1 ----
    gemm128<1, false, true, false><<<gemm_blocks, 256, GEMM_SMEM>>>(
        x, agg, nullptr, nullptr, c1_w1, c1_b1, y, NN, cs1, cq1, nullptr, nullptr);
    bn_finalize<<<1, 128>>>(cs1, cq1, c1_g, c1_be, scale, shift, NN);
    gemm128<2, true, false, false><<<gemm_blocks, 256, GEMM_SMEM>>>(
        y, nullptr, scale, shift, c1_w2, c1_b2, h, NN, nullptr, nullptr, nullptr, nullptr);

    // ---- conv2 ----
    zero_f<<<4096, 256>>>(agg, NN * DIM);
    edge_agg<<<edge_blocks, 256>>>(h, srcp, dstp, agg, EE);
    gemm128<1, false, true, false><<<gemm_blocks, 256, GEMM_SMEM>>>(
        h, agg, nullptr, nullptr, c2_w1, c2_b1, y, NN, cs2, cq2, nullptr, nullptr);
    bn_finalize<<<1, 128>>>(cs2, cq2, c2_g, c2_be, scale, shift, NN);
    // final GEMM: relu output pooled directly into pool[batch[row]]; h not materialized
    gemm128<2, true, false, true><<<gemm_blocks, 256, GEMM_SMEM>>>(
        y, nullptr, scale, shift, c2_w2, c2_b2, nullptr, NN, nullptr, nullptr, batchp, pool);

    // ---- head ----
    head_kernel<<<GG, 128>>>(pool, gl1_w, gl1_b, gl2_w, gl2_b, code, fin_w, fin_b, out);
}

// round 7
// speedup vs baseline: 1.6151x; 1.4560x over previous
#include <cuda_runtime.h>
#include <math.h>
#include <stdint.h>

#define NN 100000
#define EE 500000
#define GG 2048
#define DIM 128
#define OUTD 64
#define BN_EPS 1e-5f

// ---------------- scratch (device globals; no allocation allowed) ----------------
__device__ float g_agg[NN * DIM];
__device__ float g_y[NN * DIM];
__device__ float g_h[NN * DIM];
__device__ float g_pool[GG * DIM];
__device__ float g_code[GG * OUTD];
__device__ float g_colsum1[DIM];
__device__ float g_colsumsq1[DIM];
__device__ float g_colsum2[DIM];
__device__ float g_colsumsq2[DIM];
__device__ float g_scale[DIM];
__device__ float g_shift[DIM];
__device__ int g_src[EE];
__device__ int g_dst[EE];
__device__ int g_batch[NN];

// ---------------- packed f32x2 + reduction helpers (Blackwell) ----------------
__device__ __forceinline__ void ffma2(unsigned long long& d, unsigned long long a,
                                      unsigned long long b) {
    asm("fma.rn.f32x2 %0, %1, %2, %0;" : "+l"(d) : "l"(a), "l"(b));
}
__device__ __forceinline__ float2 unpack2(unsigned long long v) {
    float2 r;
    asm("mov.b64 {%0, %1}, %2;" : "=f"(r.x), "=f"(r.y) : "l"(v));
    return r;
}
__device__ __forceinline__ void red_add_v4(float* p, float a, float b, float c, float d) {
    asm volatile("red.global.add.v4.f32 [%0], {%1, %2, %3, %4};"
                 :: "l"(p), "f"(a), "f"(b), "f"(c), "f"(d) : "memory");
}

// ---------------- index canonicalization (dtype-robust) + agg zeroing ----------------
__device__ __forceinline__ bool is_int64_layout(const int* raw, int n_vals) {
    int nchk = n_vals < 64 ? n_vals : 64;
    for (int i = 0; i < nchk; i++)
        if (raw[2 * i + 1] != 0) return false;
    return true;
}

__global__ void convert_edges_zero(const int* __restrict__ raw, int* __restrict__ src,
                                   int* __restrict__ dst, float* __restrict__ agg) {
    bool w = is_int64_layout(raw, 2 * EE);
    int i = blockIdx.x * blockDim.x + threadIdx.x;
    int stride = gridDim.x * blockDim.x;
    if (w) {
        const long long* r = (const long long*)raw;
        for (int e = i; e < EE; e += stride) {
            src[e] = (int)r[e];
            dst[e] = (int)r[EE + e];
        }
    } else {
        for (int e = i; e < EE; e += stride) {
            src[e] = raw[e];
            dst[e] = raw[EE + e];
        }
    }
    float4* a4 = (float4*)agg;
    int n4 = NN * DIM / 4;
    for (int k = i; k < n4; k += stride) a4[k] = make_float4(0.f, 0.f, 0.f, 0.f);
}

// batch conversion + pool/stat zeroing
__global__ void convert_batch(const int* __restrict__ raw, int* __restrict__ out,
                              float* __restrict__ pool,
                              float* __restrict__ cs1, float* __restrict__ cq1,
                              float* __restrict__ cs2, float* __restrict__ cq2) {
    bool w = is_int64_layout(raw, NN);
    int i = blockIdx.x * blockDim.x + threadIdx.x;
    int stride = gridDim.x * blockDim.x;
    if (w) {
        const long long* r = (const long long*)raw;
        for (int n = i; n < NN; n += stride) out[n] = (int)r[n];
    } else {
        for (int n = i; n < NN; n += stride) out[n] = raw[n];
    }
    if (i < GG * DIM / 4) ((float4*)pool)[i] = make_float4(0.f, 0.f, 0.f, 0.f);
    if (i < DIM) { cs1[i] = 0.f; cq1[i] = 0.f; cs2[i] = 0.f; cq2[i] = 0.f; }
}

// ---------------- utility ----------------
__global__ void zero_f(float* __restrict__ p, int n) {
    int i = blockIdx.x * blockDim.x + threadIdx.x;
    int stride = gridDim.x * blockDim.x;
    float4* p4 = (float4*)p;
    int n4 = n >> 2;
    for (int k = i; k < n4; k += stride) p4[k] = make_float4(0.f, 0.f, 0.f, 0.f);
}

// ---------------- edge aggregation (32 lanes/edge, red.v4) ----------------
__global__ void edge_agg(const float* __restrict__ h, const int* __restrict__ src,
                         const int* __restrict__ dst, float* __restrict__ agg, int E) {
    int t = blockIdx.x * blockDim.x + threadIdx.x;
    int e = t >> 5;
    int lane = t & 31;
    if (e >= E) return;
    int s = src[e];
    int d = dst[e];
    if ((unsigned)s >= NN || (unsigned)d >= NN) return;
    float4 v = ((const float4*)(h + (size_t)s * DIM))[lane];
    red_add_v4(agg + (size_t)d * DIM + lane * 4, v.x, v.y, v.z, v.w);
}

// ---------------- pooling (separate kernel; fused version regressed in R6) ----------
__global__ void pool_kernel(const float* __restrict__ h, const int* __restrict__ batch,
                            float* __restrict__ pool, int n_nodes) {
    int t = blockIdx.x * blockDim.x + threadIdx.x;
    int n = t >> 5;
    int lane = t & 31;
    if (n >= n_nodes) return;
    int g = batch[n];
    if ((unsigned)g >= GG) return;
    float4 v = ((const float4*)(h + (size_t)n * DIM))[lane];
    red_add_v4(pool + (size_t)g * DIM + lane * 4, v.x, v.y, v.z, v.w);
}

// ---------------- BN finalize ----------------
__global__ void bn_finalize(const float* __restrict__ colsum, const float* __restrict__ colsumsq,
                            const float* __restrict__ gamma, const float* __restrict__ beta,
                            float* __restrict__ scale, float* __restrict__ shift, int M) {
    int c = threadIdx.x;
    if (c >= DIM) return;
    float invM = 1.f / (float)M;
    float mean = colsum[c] * invM;
    float var = colsumsq[c] * invM - mean * mean;
    float sc = gamma[c] * rsqrtf(var + BN_EPS);
    scale[c] = sc;
    shift[c] = beta[c] - mean * sc;
}

// ---------------- FFMA2 GEMM: C[M,128] = act(A'[M,128] @ W[128,128] + b) --------------
// Packed f32x2 over k-pairs: A float4 smem loads (warp-broadcast) reinterpret as 2 f32x2;
// W staged transposed Wt[col][k] (stride 132, conflict-free LDS.128).
// Thread (warp=rid, lane=cid): rows rid*8..+7, cols cid+{0,32,64,96}.
// IN_MODE 1: A' = A0 + A1 ; 2: A' = relu(scale*A0 + shift)
// STATS: fused column sum/sumsq of pre-activation output.
#define WT_STRIDE 132
#define OFF_WT 0
#define OFF_A (128 * WT_STRIDE * 4)                  // 67584
#define GEMM_SMEM (OFF_A + 64 * 128 * 4)             // 100352

template <int IN_MODE, bool OUT_RELU, bool STATS>
__global__ __launch_bounds__(256, 2) void gemm128(
    const float* __restrict__ A0, const float* __restrict__ A1,
    const float* __restrict__ scale, const float* __restrict__ shift,
    const float* __restrict__ W, const float* __restrict__ bias,
    float* __restrict__ C, int M,
    float* __restrict__ colsum, float* __restrict__ colsumsq) {
    extern __shared__ float sm[];
    float* Wt = sm + OFF_WT / 4;
    float* Asm = sm + OFF_A / 4;
    __shared__ float sbias[128];
    __shared__ float scs[128], scq[128];
    int tid = threadIdx.x;
    int row0 = blockIdx.x * 64;

    // stage W transposed: 4x4 blocks through registers
    {
        const float4* Wv = (const float4*)W;
#pragma unroll
        for (int i = 0; i < 4; i++) {
            int idx = tid + i * 256;      // 1024 blocks
            int kb = idx >> 5, cb = idx & 31;
            int k0 = kb * 4, c0 = cb * 4;
            float4 r0 = Wv[(k0 + 0) * 32 + cb];
            float4 r1 = Wv[(k0 + 1) * 32 + cb];
            float4 r2 = Wv[(k0 + 2) * 32 + cb];
            float4 r3 = Wv[(k0 + 3) * 32 + cb];
            *(float4*)(Wt + (c0 + 0) * WT_STRIDE + k0) = make_float4(r0.x, r1.x, r2.x, r3.x);
            *(float4*)(Wt + (c0 + 1) * WT_STRIDE + k0) = make_float4(r0.y, r1.y, r2.y, r3.y);
            *(float4*)(Wt + (c0 + 2) * WT_STRIDE + k0) = make_float4(r0.z, r1.z, r2.z, r3.z);
            *(float4*)(Wt + (c0 + 3) * WT_STRIDE + k0) = make_float4(r0.w, r1.w, r2.w, r3.w);
        }
    }
    if (tid < 128) {
        sbias[tid] = bias[tid];
        if (STATS) { scs[tid] = 0.f; scq[tid] = 0.f; }
    }
    // stage A tile with input transform
    {
        float4* Asv = (float4*)Asm;
#pragma unroll
        for (int i = 0; i < 8; i++) {
            int idx = tid + i * 256;
            int r = idx >> 5;
            int c4 = idx & 31;
            int gr = row0 + r;
            float4 v = make_float4(0.f, 0.f, 0.f, 0.f);
            if (gr < M) {
                v = ((const float4*)A0)[(size_t)gr * 32 + c4];
                if (IN_MODE == 1) {
                    float4 u = ((const float4*)A1)[(size_t)gr * 32 + c4];
                    v.x += u.x; v.y += u.y; v.z += u.z; v.w += u.w;
                } else if (IN_MODE == 2) {
                    float4 sc = ((const float4*)scale)[c4];
                    float4 sh = ((const float4*)shift)[c4];
                    v.x = fmaxf(v.x * sc.x + sh.x, 0.f);
                    v.y = fmaxf(v.y * sc.y + sh.y, 0.f);
                    v.z = fmaxf(v.z * sc.z + sh.z, 0.f);
                    v.w = fmaxf(v.w * sc.w + sh.w, 0.f);
                }
            }
            Asv[idx] = v;
        }
    }
    __syncthreads();

    int rid = tid >> 5;  // warp -> rows rid*8..+7
    int cid = tid & 31;  // lane -> cols cid + {0,32,64,96}
    unsigned long long acc[8][4];
#pragma unroll
    for (int i = 0; i < 8; i++)
#pragma unroll
        for (int c = 0; c < 4; c++) acc[i][c] = 0ull;

    const float4* Asv = (const float4*)Asm;
#pragma unroll
    for (int k4 = 0; k4 < 32; k4++) {
        unsigned long long a2[8][2];
#pragma unroll
        for (int i = 0; i < 8; i++) {
            float4 av = Asv[(rid * 8 + i) * 32 + k4];  // warp-broadcast
            a2[i][0] = *(unsigned long long*)&av.x;
            a2[i][1] = *(unsigned long long*)&av.z;
        }
#pragma unroll
        for (int c = 0; c < 4; c++) {
            float4 wv = *(const float4*)(Wt + (cid + 32 * c) * WT_STRIDE + k4 * 4);
            unsigned long long w0 = *(unsigned long long*)&wv.x;
            unsigned long long w1 = *(unsigned long long*)&wv.z;
#pragma unroll
            for (int i = 0; i < 8; i++) {
                ffma2(acc[i][c], a2[i][0], w0);
                ffma2(acc[i][c], a2[i][1], w1);
            }
        }
    }

    // epilogue
    float cs[4] = {0.f, 0.f, 0.f, 0.f};
    float cq[4] = {0.f, 0.f, 0.f, 0.f};
#pragma unroll
    for (int i = 0; i < 8; i++) {
        int gr = row0 + rid * 8 + i;
        if (gr < M) {
#pragma unroll
            for (int c = 0; c < 4; c++) {
                int col = cid + 32 * c;
                float2 p = unpack2(acc[i][c]);
                float y = p.x + p.y + sbias[col];
                if (STATS) { cs[c] += y; cq[c] += y * y; }
                C[(size_t)gr * 128 + col] = OUT_RELU ? fmaxf(y, 0.f) : y;
            }
        }
    }
    if (STATS) {
#pragma unroll
        for (int c = 0; c < 4; c++) {
            atomicAdd(&scs[cid + 32 * c], cs[c]);
            atomicAdd(&scq[cid + 32 * c], cq[c]);
        }
        __syncthreads();
        if (tid < 128) {
            atomicAdd(&colsum[tid], scs[tid]);
            atomicAdd(&colsumsq[tid], scq[tid]);
        }
    }
}

// ---------------- code MLP branch ----------------
__global__ void code_mlp(const float* __restrict__ code_x,
                         const float* __restrict__ w1, const float* __restrict__ b1,
                         const float* __restrict__ w2, const float* __restrict__ b2,
                         const float* __restrict__ w3, const float* __restrict__ b3,
                         float* __restrict__ code_out) {
    __shared__ float buf0[128], buf1[128];
    __shared__ float red[64];
    __shared__ float s_mx, s_lse;
    int g = blockIdx.x, j = threadIdx.x;
    buf0[j] = code_x[(size_t)g * 128 + j];
    __syncthreads();
    float acc = b1[j];
    for (int k = 0; k < 128; k++) acc += buf0[k] * w1[k * 128 + j];
    buf1[j] = fmaxf(acc, 0.f);
    __syncthreads();
    float acc2 = b2[j];
    for (int k = 0; k < 128; k++) acc2 += buf1[k] * w2[k * 128 + j];
    buf0[j] = fmaxf(acc2, 0.f);
    __syncthreads();
    float v = 0.f;
    if (j < 64) {
        v = b3[j];
        for (int k = 0; k < 128; k++) v += buf0[k] * w3[k * 64 + j];
        red[j] = v;
    }
    __syncthreads();
    if (j == 0) {
        float m = red[0];
        for (int i = 1; i < 64; i++) m = fmaxf(m, red[i]);
        float s = 0.f;
        for (int i = 0; i < 64; i++) s += expf(red[i] - m);
        s_mx = m;
        s_lse = logf(s);
    }
    __syncthreads();
    if (j < 64) code_out[(size_t)g * 64 + j] = v - s_mx - s_lse;
}

// ---------------- head ----------------
__global__ void head_kernel(const float* __restrict__ pool,
                            const float* __restrict__ l1w, const float* __restrict__ l1b,
                            const float* __restrict__ l2w, const float* __restrict__ l2b,
                            const float* __restrict__ code,
                            const float* __restrict__ finw, const float* __restrict__ finb,
                            float* __restrict__ out) {
    __shared__ float p[128], t[128], cc[128];
    __shared__ float r0[128], r1[128];
    int g = blockIdx.x, j = threadIdx.x;
    p[j] = pool[(size_t)g * 128 + j];
    __syncthreads();
    float a = l1b[j];
    for (int k = 0; k < 128; k++) a += p[k] * l1w[k * 128 + j];
    t[j] = fmaxf(a, 0.f);
    __syncthreads();
    if (j < 64) {
        float v = l2b[j];
        for (int k = 0; k < 128; k++) v += t[k] * l2w[k * 64 + j];
        cc[64 + j] = v;
        cc[j] = code[(size_t)g * 64 + j];
    }
    __syncthreads();
    r0[j] = cc[j] * finw[j * 2 + 0];
    r1[j] = cc[j] * finw[j * 2 + 1];
    __syncthreads();
    if (j == 0) {
        float o0 = finb[0], o1 = finb[1];
        for (int k = 0; k < 128; k++) { o0 += r0[k]; o1 += r1[k]; }
        float m = fmaxf(o0, o1);
        float l = m + logf(expf(o0 - m) + expf(o1 - m));
        out[(size_t)g * 2 + 0] = o0 - l;
        out[(size_t)g * 2 + 1] = o1 - l;
    }
}

// ---------------- launcher ----------------
extern "C" void kernel_launch(void* const* d_in, const int* in_sizes, int n_in,
                              void* d_out, int out_size) {
    const float* x = (const float*)d_in[0];
    const int* ei_raw = (const int*)d_in[1];
    const int* batch_raw = (const int*)d_in[2];
    const float* code_x = (const float*)d_in[3];
    const float* c1_w1 = (const float*)d_in[4];
    const float* c1_b1 = (const float*)d_in[5];
    const float* c1_g = (const float*)d_in[6];
    const float* c1_be = (const float*)d_in[7];
    const float* c1_w2 = (const float*)d_in[8];
    const float* c1_b2 = (const float*)d_in[9];
    const float* c2_w1 = (const float*)d_in[10];
    const float* c2_b1 = (const float*)d_in[11];
    const float* c2_g = (const float*)d_in[12];
    const float* c2_be = (const float*)d_in[13];
    const float* c2_w2 = (const float*)d_in[14];
    const float* c2_b2 = (const float*)d_in[15];
    const float* gl1_w = (const float*)d_in[16];
    const float* gl1_b = (const float*)d_in[17];
    const float* gl2_w = (const float*)d_in[18];
    const float* gl2_b = (const float*)d_in[19];
    const float* fc1_w = (const float*)d_in[20];
    const float* fc1_b = (const float*)d_in[21];
    const float* fc2_w = (const float*)d_in[22];
    const float* fc2_b = (const float*)d_in[23];
    const float* fc3_w = (const float*)d_in[24];
    const float* fc3_b = (const float*)d_in[25];
    const float* fin_w = (const float*)d_in[26];
    const float* fin_b = (const float*)d_in[27];
    float* out = (float*)d_out;

    float *agg, *y, *h, *pool, *code, *cs1, *cq1, *cs2, *cq2, *scale, *shift;
    int *srcp, *dstp, *batchp;
    cudaGetSymbolAddress((void**)&agg, g_agg);
    cudaGetSymbolAddress((void**)&y, g_y);
    cudaGetSymbolAddress((void**)&h, g_h);
    cudaGetSymbolAddress((void**)&pool, g_pool);
    cudaGetSymbolAddress((void**)&code, g_code);
    cudaGetSymbolAddress((void**)&cs1, g_colsum1);
    cudaGetSymbolAddress((void**)&cq1, g_colsumsq1);
    cudaGetSymbolAddress((void**)&cs2, g_colsum2);
    cudaGetSymbolAddress((void**)&cq2, g_colsumsq2);
    cudaGetSymbolAddress((void**)&scale, g_scale);
    cudaGetSymbolAddress((void**)&shift, g_shift);
    cudaGetSymbolAddress((void**)&srcp, g_src);
    cudaGetSymbolAddress((void**)&dstp, g_dst);
    cudaGetSymbolAddress((void**)&batchp, g_batch);

    cudaFuncSetAttribute(gemm128<1, false, true>, cudaFuncAttributeMaxDynamicSharedMemorySize, GEMM_SMEM);
    cudaFuncSetAttribute(gemm128<2, true, false>, cudaFuncAttributeMaxDynamicSharedMemorySize, GEMM_SMEM);

    const int gemm_blocks = (NN + 63) / 64;           // 1563
    const int edge_blocks = (EE * 32 + 255) / 256;    // 62500

    convert_edges_zero<<<2048, 256>>>(ei_raw, srcp, dstp, agg);                        // 0
    edge_agg<<<edge_blocks, 256>>>(x, srcp, dstp, agg, EE);                            // 1
    convert_batch<<<256, 256>>>(batch_raw, batchp, pool, cs1, cq1, cs2, cq2);          // 2

    // ---- conv1 ----
    gemm128<1, false, true><<<gemm_blocks, 256, GEMM_SMEM>>>(                          // 3 (profiled)
        x, agg, nullptr, nullptr, c1_w1, c1_b1, y, NN, cs1, cq1);
    code_mlp<<<GG, 128>>>(code_x, fc1_w, fc1_b, fc2_w, fc2_b, fc3_w, fc3_b, code);     // 4
    bn_finalize<<<1, 128>>>(cs1, cq1, c1_g, c1_be, scale, shift, NN);                  // 5
    gemm128<2, true, false><<<gemm_blocks, 256, GEMM_SMEM>>>(
        y, nullptr, scale, shift, c1_w2, c1_b2, h, NN, nullptr, nullptr);

    // ---- conv2 ----
    zero_f<<<4096, 256>>>(agg, NN * DIM);
    edge_agg<<<edge_blocks, 256>>>(h, srcp, dstp, agg, EE);
    gemm128<1, false, true><<<gemm_blocks, 256, GEMM_SMEM>>>(
        h, agg, nullptr, nullptr, c2_w1, c2_b1, y, NN, cs2, cq2);
    bn_finalize<<<1, 128>>>(cs2, cq2, c2_g, c2_be, scale, shift, NN);
    gemm128<2, true, false><<<gemm_blocks, 256, GEMM_SMEM>>>(
        y, nullptr, scale, shift, c2_w2, c2_b2, h, NN, nullptr, nullptr);

    // ---- pool + head ----
    pool_kernel<<<(NN * 32 + 255) / 256, 256>>>(h, batchp, pool, NN);
    head_kernel<<<GG, 128>>>(pool, gl1_w, gl1_b, gl2_w, gl2_b, code, fin_w, fin_b, out);
}